// round 11
// baseline (speedup 1.0000x reference)
#include <cuda_runtime.h>
#include <cstdint>

typedef unsigned long long u64;

#define HW 3136  // 56*56

__device__ __forceinline__ u64 pack2(float a, float b) {
    u64 r; asm("mov.b64 %0, {%1,%2};" : "=l"(r) : "f"(a), "f"(b)); return r;
}
__device__ __forceinline__ float2 unpack2(u64 a) {
    float2 r; asm("mov.b64 {%0,%1}, %2;" : "=f"(r.x), "=f"(r.y) : "l"(a)); return r;
}
__device__ __forceinline__ u64 fma2(u64 a, u64 b, u64 c) {
    u64 d; asm("fma.rn.f32x2 %0, %1, %2, %3;" : "=l"(d) : "l"(a), "l"(b), "l"(c)); return d;
}
__device__ __forceinline__ void stcs4(float* p, float4 v) {
    asm volatile("st.global.cs.v4.f32 [%0], {%1,%2,%3,%4};"
                 :: "l"(p), "f"(v.x), "f"(v.y), "f"(v.z), "f"(v.w) : "memory");
}

// ---- mbarrier + bulk-copy helpers (single-thread producer path) ----
__device__ __forceinline__ void mb_init(uint32_t a, uint32_t cnt) {
    asm volatile("mbarrier.init.shared.b64 [%0], %1;" :: "r"(a), "r"(cnt) : "memory");
}
__device__ __forceinline__ void mb_expect(uint32_t a, uint32_t bytes) {
    asm volatile("mbarrier.arrive.expect_tx.shared.b64 _, [%0], %1;"
                 :: "r"(a), "r"(bytes) : "memory");
}
__device__ __forceinline__ void mb_wait(uint32_t a, uint32_t parity) {
    asm volatile(
        "{\n\t.reg .pred P;\n"
        "LAB_%=:\n\t"
        "mbarrier.try_wait.parity.acquire.cta.shared::cta.b64 P, [%0], %1, 0x989680;\n\t"
        "@!P bra LAB_%=;\n\t}"
        :: "r"(a), "r"(parity) : "memory");
}
__device__ __forceinline__ void bulk_g2s(uint32_t dst, const float* src,
                                         uint32_t bytes, uint32_t mbar) {
    asm volatile(
        "cp.async.bulk.shared::cta.global.mbarrier::complete_tx::bytes [%0], [%1], %2, [%3];"
        :: "r"(dst), "l"(src), "r"(bytes), "r"(mbar) : "memory");
}

#define NSLOT 11                    // slots 0..9 = rows m0-2..m0+7; slot 10 = wrap row 55
#define XS_BUF (2 * NSLOT * 56)     // 2 channels/chunk, 1232 floats = 4928 B per buffer
#define CH_STRIDE_B 2464            // NSLOT*56*4 bytes per channel in a buffer

// Issue the bulk loads for chunk c (channels 2c, 2c+1) into buffer at dstb.
// Interior blocks: rows m0-2..m0+7 are one contiguous 2240B span per channel.
// m0==0: rows 0..7 (1792B) into slot 2, wrap row 55 (224B) into slot 10
//        (slots 0/1 are never read for m0==0 by construction).
__device__ __forceinline__ void issue_chunk(const float* xl, int m0,
                                            uint32_t dstb, uint32_t mb, int c) {
    const float* s0 = xl + (size_t)(2 * c) * HW;
    if (m0 > 0) {
        mb_expect(mb, 4480);
        const float* r = s0 + (m0 - 2) * 56;
        bulk_g2s(dstb,               r,       2240, mb);
        bulk_g2s(dstb + CH_STRIDE_B, r + HW,  2240, mb);
    } else {
        mb_expect(mb, 4032);
        bulk_g2s(dstb + 448,                s0,            1792, mb);
        bulk_g2s(dstb + 2240,               s0 + 55 * 56,  224,  mb);
        bulk_g2s(dstb + CH_STRIDE_B + 448,  s0 + HW,       1792, mb);
        bulk_g2s(dstb + CH_STRIDE_B + 2240, s0 + HW + 55 * 56, 224, mb);
    }
}

// ---------------------------------------------------------------------------
// Fused: block = (l, 8-row m chunk). 224 threads = (wq:14, mloc:8, h:2).
// Phase 1: x staged via double-buffered cp.async.bulk (1 kk per chunk, 64
//   chunks), tid0 producer + mbarrier, barrier-broadcast to consumers;
//   packed f32x2 FMA; T tile kept in smem Ts[mi][ij][64] (edge cols zero).
// Phase 2: 3-tap conv along w; f32x2 packed over adjacent n; .cs stores.
// 6 blocks/SM: smem ~34 KB, regs capped 48.
// ---------------------------------------------------------------------------
__global__ __launch_bounds__(224, 6) void fused(const float* __restrict__ x,
                                                const float* __restrict__ w1,
                                                const float* __restrict__ w2,
                                                float* __restrict__ out) {
    __shared__ __align__(16) float xs[2][XS_BUF];   //  9856 B
    __shared__ u64   w1p[768];        //  6144 B  stage-1 weights, (w,w) dup pairs
    __shared__ u64   w2d[192];        //  1536 B  stage-2 weights, (w,w) dup pairs
    __shared__ float Ts[8 * 8 * 64];  // 16384 B  [mi][ij][4+w]
    __shared__ __align__(8) u64 mbar[2];

    int tid = threadIdx.x;
    int m0  = blockIdx.x * 8;
    int l   = blockIdx.y;

    // ---- weights + Ts edge zeroing + mbarrier init ----
    for (int i = tid; i < 768; i += 224) { float w = w1[i]; w1p[i] = pack2(w, w); }
    if (tid < 192) { float w = w2[tid]; w2d[tid] = pack2(w, w); }
    for (int i = tid; i < 64 * 8; i += 224) {       // 64 rows x 8 edge cols
        int r = i >> 3, c = i & 7;
        Ts[r * 64 + (c < 4 ? c : 56 + c)] = 0.0f;   // cols 0..3 and 60..63
    }
    uint32_t mbu[2] = { (uint32_t)__cvta_generic_to_shared(&mbar[0]),
                        (uint32_t)__cvta_generic_to_shared(&mbar[1]) };
    if (tid == 0) { mb_init(mbu[0], 1); mb_init(mbu[1], 1); }
    __syncthreads();

    // ---- thread decode ----
    int wq   = tid % 14;
    int mloc = (tid / 14) % 8;
    int h    = tid / 112;        // i-half in phase 1, j-half in phase 2
    int m    = m0 + mloc;
    int w0   = wq * 4;

    // per-(m,tap) smem slot + validity (stage-1 H taps with +1 circular roll)
    int  slot[3];
    bool val[3];
#pragma unroll
    for (int tap = 0; tap < 3; tap++) {
        int hp    = m + tap - 1;
        val[tap]  = (hp >= 0) && (hp < 56);
        slot[tap] = (hp == 0) ? 10 : (mloc + tap);
    }

    const float* xl = x + (size_t)l * 128 * HW;
    uint32_t xsb[2] = { (uint32_t)__cvta_generic_to_shared(&xs[0][0]),
                        (uint32_t)__cvta_generic_to_shared(&xs[1][0]) };

    u64 acc[4][2];  // [j][w-pair]
#pragma unroll
    for (int j = 0; j < 4; j++) { acc[j][0] = 0ull; acc[j][1] = 0ull; }

    // producer prologue: chunk 0 into buffer 0
    if (tid == 0) issue_chunk(xl, m0, xsb[0], mbu[0], 0);

    uint32_t ph0 = 0, ph1 = 0;   // mbarrier phase parity (tid0 only)

    // ---- phase 1 main loop: 64 chunks of 2 channels (one kk each) ----
#pragma unroll 2
    for (int kk = 0; kk < 64; kk++) {
        int b = kk & 1;
        if (tid == 0) {
            if (b) { mb_wait(mbu[1], ph1); ph1 ^= 1; }
            else   { mb_wait(mbu[0], ph0); ph0 ^= 1; }
        }
        __syncthreads();   // data broadcast + all threads done with chunk kk-1
        if (tid == 0 && kk + 1 < 64)
            issue_chunk(xl, m0, xsb[b ^ 1], mbu[b ^ 1], kk + 1);

        const float* xb = xs[b];
#pragma unroll
        for (int tap = 0; tap < 3; tap++) {
            if (val[tap]) {
                ulonglong2 wa = *reinterpret_cast<const ulonglong2*>(&w1p[kk * 12 + tap * 4]);
                ulonglong2 wb = *reinterpret_cast<const ulonglong2*>(&w1p[kk * 12 + tap * 4 + 2]);
                ulonglong2 xp = *reinterpret_cast<const ulonglong2*>(
                    &xb[(h * NSLOT + slot[tap]) * 56 + w0]);
                acc[0][0] = fma2(xp.x, wa.x, acc[0][0]);
                acc[0][1] = fma2(xp.y, wa.x, acc[0][1]);
                acc[1][0] = fma2(xp.x, wa.y, acc[1][0]);
                acc[1][1] = fma2(xp.y, wa.y, acc[1][1]);
                acc[2][0] = fma2(xp.x, wb.x, acc[2][0]);
                acc[2][1] = fma2(xp.y, wb.x, acc[2][1]);
                acc[3][0] = fma2(xp.x, wb.y, acc[3][0]);
                acc[3][1] = fma2(xp.y, wb.y, acc[3][1]);
            }
        }
    }

    // ---- write T tile to smem: Ts[mloc][ij][4 + w] ----
#pragma unroll
    for (int j = 0; j < 4; j++) {
        float2 a0 = unpack2(acc[j][0]);   // w0, w0+1
        float2 a1 = unpack2(acc[j][1]);   // w0+2, w0+3
        int ij = h * 4 + j;
        *reinterpret_cast<float4*>(&Ts[(mloc * 8 + ij) * 64 + 4 + w0]) =
            make_float4(a0.x, a0.y, a1.x, a1.y);
    }
    __syncthreads();

    // ---- phase 2: thread = (mloc, nq=wq, jh=h); n = w0..w0+3, 16 j, 4 oo ----
    float* ob = out + (size_t)l * 128 * HW + m * 56 + w0;

#pragma unroll
    for (int oo = 0; oo < 4; oo++) {
        // shifted n-pairs P[i2][k'] = (t[k'], t[k'+1]), k' = 0..4
        u64 P[2][5];
#pragma unroll
        for (int i2 = 0; i2 < 2; i2++) {
            const float* r = &Ts[(mloc * 8 + i2 * 4 + oo) * 64 + 3 + w0];
            float t0 = r[0], t1 = r[1], t2 = r[2], t3 = r[3], t4 = r[4], t5 = r[5];
            P[i2][0] = pack2(t0, t1);
            P[i2][1] = pack2(t1, t2);
            P[i2][2] = pack2(t2, t3);
            P[i2][3] = pack2(t3, t4);
            P[i2][4] = pack2(t4, t5);
        }

#pragma unroll 4
        for (int jj = 0; jj < 16; jj++) {
            int j = h * 16 + jj;
            u64 rrA = 0ull, rrB = 0ull;
#pragma unroll
            for (int i2 = 0; i2 < 2; i2++) {
                u64 wk0 = w2d[i2 * 96 + j];
                u64 wk1 = w2d[i2 * 96 + 32 + j];
                u64 wk2 = w2d[i2 * 96 + 64 + j];
                rrA = fma2(P[i2][0], wk0, rrA);
                rrA = fma2(P[i2][1], wk1, rrA);
                rrA = fma2(P[i2][2], wk2, rrA);
                rrB = fma2(P[i2][2], wk0, rrB);
                rrB = fma2(P[i2][3], wk1, rrB);
                rrB = fma2(P[i2][4], wk2, rrB);
            }
            float2 eA = unpack2(rrA);
            float2 eB = unpack2(rrB);
            stcs4(ob + (size_t)(4 * j + oo) * HW, make_float4(eA.x, eA.y, eB.x, eB.y));
        }
    }
}

// ---------------------------------------------------------------------------
extern "C" void kernel_launch(void* const* d_in, const int* in_sizes, int n_in,
                              void* d_out, int out_size) {
    const float* x  = nullptr;
    const float* w1 = nullptr;
    const float* w2 = nullptr;
    for (int i = 0; i < n_in; i++) {
        if (in_sizes[i] == 128 * 128 * 56 * 56) x  = (const float*)d_in[i];
        else if (in_sizes[i] == 64 * 3 * 4)     w1 = (const float*)d_in[i];
        else if (in_sizes[i] == 2 * 3 * 32)     w2 = (const float*)d_in[i];
    }
    if (!x)  x  = (const float*)d_in[0];
    if (!w1) w1 = (const float*)d_in[1];
    if (!w2) w2 = (const float*)d_in[2];

    fused<<<dim3(7, 128), 224>>>(x, w1, w2, (float*)d_out);
}

// round 13
// speedup vs baseline: 1.3993x; 1.3993x over previous
#include <cuda_runtime.h>
#include <cstdint>

typedef unsigned long long u64;

#define HW 3136  // 56*56

__device__ __forceinline__ u64 pack2(float a, float b) {
    u64 r; asm("mov.b64 %0, {%1,%2};" : "=l"(r) : "f"(a), "f"(b)); return r;
}
__device__ __forceinline__ float2 unpack2(u64 a) {
    float2 r; asm("mov.b64 {%0,%1}, %2;" : "=f"(r.x), "=f"(r.y) : "l"(a)); return r;
}
__device__ __forceinline__ u64 fma2(u64 a, u64 b, u64 c) {
    u64 d; asm("fma.rn.f32x2 %0, %1, %2, %3;" : "=l"(d) : "l"(a), "l"(b), "l"(c)); return d;
}
__device__ __forceinline__ void cpa16(uint32_t dst, const void* src) {
    asm volatile("cp.async.cg.shared.global [%0], [%1], 16;" :: "r"(dst), "l"(src));
}
__device__ __forceinline__ void cpa_commit() { asm volatile("cp.async.commit_group;" ::: "memory"); }
__device__ __forceinline__ void cpa_wait0()  { asm volatile("cp.async.wait_group 0;"  ::: "memory"); }
__device__ __forceinline__ void stcs4(float* p, float4 v) {
    asm volatile("st.global.cs.v4.f32 [%0], {%1,%2,%3,%4};"
                 :: "l"(p), "f"(v.x), "f"(v.y), "f"(v.z), "f"(v.w) : "memory");
}

#define NSLOT 10                  // slots 0..9; interior: rows m0-2..m0+7. m0==0: slot0=row55(wrap)
#define CCH 4                     // channels per chunk (2 kk)
#define XSBUF_B (CCH * NSLOT * 56 * 4)   // 8960 B per buffer
#define NLOAD (CCH * NSLOT * 14)         // 560 float4 per chunk
#define TS_PITCH 60

// smem pool layout (bytes):
//   [0      .. 8960)   xs buffer 0        \  aliased by Ts (15376 B) after phase 1
//   [8960   .. 17920)  xs buffer 1        /
//   [17920  .. 24064)  w1p: 768 u64 dup-pairs
//   [24064  .. 25600)  w2d: 192 u64 dup-pairs
#define SMEM_BYTES 25600

// ---------------------------------------------------------------------------
// Fused: block = (l, 8-row m chunk). 224 threads = (wq:14, mloc:8, h:2).
// Phase 1: x staged via double-buffered per-thread cp.async (32 chunks of 4
//   channels); packed f32x2 FMA; T tile then written into smem aliased over xs.
// Phase 2: 3-tap conv along w; f32x2 packed over adjacent n; .cs stores.
// 6 blocks/SM: smem 25.6 KB, regs capped 48, grid 896 ~= capacity 888.
// ---------------------------------------------------------------------------
__global__ __launch_bounds__(224, 6) void fused(const float* __restrict__ x,
                                                const float* __restrict__ w1,
                                                const float* __restrict__ w2,
                                                float* __restrict__ out) {
    __shared__ __align__(16) char pool[SMEM_BYTES];
    float* xs0 = reinterpret_cast<float*>(pool);
    float* xs1 = reinterpret_cast<float*>(pool + XSBUF_B);
    u64*   w1p = reinterpret_cast<u64*>(pool + 2 * XSBUF_B);
    u64*   w2d = reinterpret_cast<u64*>(pool + 2 * XSBUF_B + 6144);
    float* Ts  = reinterpret_cast<float*>(pool);   // aliases xs0+xs1 (post-phase-1)

    int tid = threadIdx.x;
    int m0  = blockIdx.x * 8;
    int l   = blockIdx.y;

    // ---- weights (non-aliased region) ----
    for (int i = tid; i < 768; i += 224) { float w = w1[i]; w1p[i] = pack2(w, w); }
    if (tid < 192) { float w = w2[tid]; w2d[tid] = pack2(w, w); }

    // ---- thread decode ----
    int wq   = tid % 14;
    int mloc = (tid / 14) % 8;
    int h    = tid / 112;        // i-half in phase 1, j-half in phase 2
    int m    = m0 + mloc;
    int w0   = wq * 4;

    // stage-1 taps (+1 circular roll): hp = m+tap-1, valid iff hp in [0,56);
    // source row hp-1 (or 55 when hp==0). Interior: slot s holds row m0-2+s.
    // m0==0: slot0 holds wrap row 55; slots s>=2 hold rows s-2; slot1 unused.
    int  slot[3];
    bool val[3];
#pragma unroll
    for (int tap = 0; tap < 3; tap++) {
        int hp    = m + tap - 1;
        val[tap]  = (hp >= 0) && (hp < 56);
        slot[tap] = (hp == 0) ? 0 : (mloc + tap);
    }

    // ---- cooperative loader precompute: 3 slots/thread (560 = 2.5 x 224) ----
    const float* xl = x + (size_t)l * 128 * HW;
    int  goff[3];
    int  soff[3];
    bool lv[3];
#pragma unroll
    for (int k = 0; k < 3; k++) {
        int idx = tid + k * 224;
        lv[k] = idx < NLOAD;
        int ii = lv[k] ? idx : 0;
        int c  = ii / (NSLOT * 14);
        int r  = ii % (NSLOT * 14);
        int s  = r / 14;
        int wf = r % 14;
        int row;
        if (m0 > 0)       row = m0 - 2 + s;                 // always in [0,55]
        else              row = (s == 0) ? 55 : max(s - 2, 0);
        goff[k] = c * HW + row * 56 + wf * 4;
        soff[k] = ((c * NSLOT + s) * 56 + wf * 4) * 4;
    }
    uint32_t xsb[2] = { (uint32_t)__cvta_generic_to_shared(xs0),
                        (uint32_t)__cvta_generic_to_shared(xs1) };

    u64 acc[4][2];  // [j][w-pair]
#pragma unroll
    for (int j = 0; j < 4; j++) { acc[j][0] = 0ull; acc[j][1] = 0ull; }

    // prefetch chunk 0
#pragma unroll
    for (int k = 0; k < 3; k++)
        if (lv[k]) cpa16(xsb[0] + soff[k], xl + goff[k]);
    cpa_commit();

    // ---- phase 1: 32 chunks of 4 channels (2 kk each) ----
    for (int ch = 0; ch < 32; ch++) {
        cpa_wait0();
        __syncthreads();               // data visible; prev buf free (orders w1p init too)
        if (ch < 31) {
            const float* cb = xl + (size_t)(ch + 1) * CCH * HW;
            uint32_t sb = xsb[(ch + 1) & 1];
#pragma unroll
            for (int k = 0; k < 3; k++)
                if (lv[k]) cpa16(sb + soff[k], cb + goff[k]);
            cpa_commit();
        }
        const float* xb = (ch & 1) ? xs1 : xs0;
#pragma unroll
        for (int kl = 0; kl < 2; kl++) {
            int kk = ch * 2 + kl;
            int cl = 2 * kl + h;       // channel within chunk for this i-half
#pragma unroll
            for (int tap = 0; tap < 3; tap++) {
                if (val[tap]) {
                    ulonglong2 wa = *reinterpret_cast<const ulonglong2*>(&w1p[kk * 12 + tap * 4]);
                    ulonglong2 wb = *reinterpret_cast<const ulonglong2*>(&w1p[kk * 12 + tap * 4 + 2]);
                    ulonglong2 xp = *reinterpret_cast<const ulonglong2*>(
                        &xb[(cl * NSLOT + slot[tap]) * 56 + w0]);
                    acc[0][0] = fma2(xp.x, wa.x, acc[0][0]);
                    acc[0][1] = fma2(xp.y, wa.x, acc[0][1]);
                    acc[1][0] = fma2(xp.x, wa.y, acc[1][0]);
                    acc[1][1] = fma2(xp.y, wa.y, acc[1][1]);
                    acc[2][0] = fma2(xp.x, wb.x, acc[2][0]);
                    acc[2][1] = fma2(xp.y, wb.x, acc[2][1]);
                    acc[3][0] = fma2(xp.x, wb.y, acc[3][0]);
                    acc[3][1] = fma2(xp.y, wb.y, acc[3][1]);
                }
            }
        }
    }

    // ---- all reads of xs done -> safe to alias Ts over it ----
    __syncthreads();

    // edge zeroing: cols 0..3 of each of 64 rows + 4 pad floats (idx 3840..3843)
    for (int idx = tid; idx < 260; idx += 224) {
        int off = (idx < 256) ? ((idx >> 2) * TS_PITCH + (idx & 3)) : (3840 + idx - 256);
        Ts[off] = 0.0f;
    }
    // write T tile: Ts[mloc*8 + ij][4 + w], pitch 60
#pragma unroll
    for (int j = 0; j < 4; j++) {
        float2 a0 = unpack2(acc[j][0]);   // w0, w0+1
        float2 a1 = unpack2(acc[j][1]);   // w0+2, w0+3
        int ij = h * 4 + j;
        *reinterpret_cast<float4*>(&Ts[(mloc * 8 + ij) * TS_PITCH + 4 + w0]) =
            make_float4(a0.x, a0.y, a1.x, a1.y);
    }
    __syncthreads();

    // ---- phase 2: thread = (mloc, nq=wq, jh=h); n = w0..w0+3, 16 j, 4 oo ----
    float* ob = out + (size_t)l * 128 * HW + m * 56 + w0;

#pragma unroll
    for (int oo = 0; oo < 4; oo++) {
        // shifted n-pairs P[i2][k'] = (t[k'], t[k'+1]), k' = 0..4
        u64 P[2][5];
#pragma unroll
        for (int i2 = 0; i2 < 2; i2++) {
            const float* r = &Ts[(mloc * 8 + i2 * 4 + oo) * TS_PITCH + 3 + w0];
            float t0 = r[0], t1 = r[1], t2 = r[2], t3 = r[3], t4 = r[4], t5 = r[5];
            P[i2][0] = pack2(t0, t1);
            P[i2][1] = pack2(t1, t2);
            P[i2][2] = pack2(t2, t3);
            P[i2][3] = pack2(t3, t4);
            P[i2][4] = pack2(t4, t5);
        }

#pragma unroll 4
        for (int jj = 0; jj < 16; jj++) {
            int j = h * 16 + jj;
            u64 rrA = 0ull, rrB = 0ull;
#pragma unroll
            for (int i2 = 0; i2 < 2; i2++) {
                u64 wk0 = w2d[i2 * 96 + j];
                u64 wk1 = w2d[i2 * 96 + 32 + j];
                u64 wk2 = w2d[i2 * 96 + 64 + j];
                rrA = fma2(P[i2][0], wk0, rrA);
                rrA = fma2(P[i2][1], wk1, rrA);
                rrA = fma2(P[i2][2], wk2, rrA);
                rrB = fma2(P[i2][2], wk0, rrB);
                rrB = fma2(P[i2][3], wk1, rrB);
                rrB = fma2(P[i2][4], wk2, rrB);
            }
            float2 eA = unpack2(rrA);
            float2 eB = unpack2(rrB);
            stcs4(ob + (size_t)(4 * j + oo) * HW, make_float4(eA.x, eA.y, eB.x, eB.y));
        }
    }
}

// ---------------------------------------------------------------------------
extern "C" void kernel_launch(void* const* d_in, const int* in_sizes, int n_in,
                              void* d_out, int out_size) {
    const float* x  = nullptr;
    const float* w1 = nullptr;
    const float* w2 = nullptr;
    for (int i = 0; i < n_in; i++) {
        if (in_sizes[i] == 128 * 128 * 56 * 56) x  = (const float*)d_in[i];
        else if (in_sizes[i] == 64 * 3 * 4)     w1 = (const float*)d_in[i];
        else if (in_sizes[i] == 2 * 3 * 32)     w2 = (const float*)d_in[i];
    }
    if (!x)  x  = (const float*)d_in[0];
    if (!w1) w1 = (const float*)d_in[1];
    if (!w2) w2 = (const float*)d_in[2];

    fused<<<dim3(7, 128), 224>>>(x, w1, w2, (float*)d_out);
}